// round 13
// baseline (speedup 1.0000x reference)
#include <cuda_runtime.h>
#include <cuda_fp16.h>
#include <cstdint>

#define BATCH 4096
#define NST   512
#define IO    16
#define DS    32
#define PTOT  8192
#define NCH   32
#define LCH   16

typedef unsigned long long ull;

// ---------------- device scratch (static; no mallocs) ----------------
__device__ __align__(16) __half g_Uh[(size_t)BATCH * PTOT];            // fp16(U)
__device__ __align__(16) __half g_Th[(size_t)NCH * 256 * 320];         // T^T per chunk [n][k]
__device__ __align__(16) __half g_Tl[(size_t)NCH * 256 * 320];
__device__ __align__(16) __half g_Sh[(size_t)NCH * 64 * 256];          // S^T per chunk [n][k]
__device__ __align__(16) __half g_Sl[(size_t)NCH * 64 * 256];
__device__ __align__(16) float g_xloc[(size_t)BATCH * NCH * 64];       // [row][c][64]
__device__ __align__(16) __half g_xinh[(size_t)BATCH * NCH * 64];      // fp16(xin)
__device__ float g_P2[2 * NCH * DS * DS];

// ---------------- f32x2 helpers ----------------
__device__ __forceinline__ ull pack2(float lo, float hi) {
    ull r; asm("mov.b64 %0, {%1, %2};" : "=l"(r) : "f"(lo), "f"(hi)); return r;
}
__device__ __forceinline__ ull dup2(float v) { return pack2(v, v); }
__device__ __forceinline__ void unpack2(ull p, float& lo, float& hi) {
    asm("mov.b64 {%0, %1}, %2;" : "=f"(lo), "=f"(hi) : "l"(p));
}
__device__ __forceinline__ ull fma2(ull a, ull b, ull c) {
    ull r; asm("fma.rn.f32x2 %0, %1, %2, %3;" : "=l"(r) : "l"(a), "l"(b), "l"(c)); return r;
}

// ---------------- cp.async helpers ----------------
__device__ __forceinline__ void cpasync16(void* s, const void* g) {
    uint32_t sa = (uint32_t)__cvta_generic_to_shared(s);
    asm volatile("cp.async.cg.shared.global [%0], [%1], 16;" :: "r"(sa), "l"(g));
}
__device__ __forceinline__ void cpcommit() { asm volatile("cp.async.commit_group;"); }
template<int N> __device__ __forceinline__ void cpwait() {
    asm volatile("cp.async.wait_group %0;" :: "n"(N));
}

// ---------------- mma.sync / ldmatrix helpers (fp16) ----------------
__device__ __forceinline__ void ldmx4(uint32_t* r, uint32_t addr) {
    asm volatile("ldmatrix.sync.aligned.m8n8.x4.shared.b16 {%0,%1,%2,%3}, [%4];"
        : "=r"(r[0]), "=r"(r[1]), "=r"(r[2]), "=r"(r[3]) : "r"(addr));
}
__device__ __forceinline__ void ldmx2(uint32_t* r, uint32_t addr) {
    asm volatile("ldmatrix.sync.aligned.m8n8.x2.shared.b16 {%0,%1}, [%2];"
        : "=r"(r[0]), "=r"(r[1]) : "r"(addr));
}
__device__ __forceinline__ void mma16816(float* c, const uint32_t* a, const uint32_t* b) {
    asm volatile(
        "mma.sync.aligned.m16n8k16.row.col.f32.f16.f16.f32 "
        "{%0,%1,%2,%3}, {%4,%5,%6,%7}, {%8,%9}, {%0,%1,%2,%3};"
        : "+f"(c[0]), "+f"(c[1]), "+f"(c[2]), "+f"(c[3])
        : "r"(a[0]), "r"(a[1]), "r"(a[2]), "r"(a[3]), "r"(b[0]), "r"(b[1]));
}
// swizzled smem offset: logical (row r, 16B chunk k8) in a [*,64]fp16 tile
__device__ __forceinline__ uint32_t swz(int r, int k8) {
    return (uint32_t)(r * 128 + ((k8 ^ (r & 7)) << 4));
}

__device__ __forceinline__ void split_f16(float v, __half& h, __half& l) {
    h = __float2half_rn(v);
    l = __float2half_rn(v - __half2float(h));
}

// =====================================================================
// 1. Convert U -> fp16 (single array)
// =====================================================================
__global__ __launch_bounds__(256)
void convertU_kernel(const float* __restrict__ U) {
    const size_t i = (size_t)blockIdx.x * 256 + threadIdx.x;
    const float4 v = ((const float4*)U)[i];
    ((__half2*)g_Uh)[2*i]   = __halves2half2(__float2half_rn(v.x), __float2half_rn(v.y));
    ((__half2*)g_Uh)[2*i+1] = __halves2half2(__float2half_rn(v.z), __float2half_rn(v.w));
}

// =====================================================================
// 2. Strip precompute -> T^T (fp16 h/l) input blocks + S^T columns
// =====================================================================
__global__ __launch_bounds__(128)
void strip_kernel(const float* __restrict__ A, const float* __restrict__ B,
                  const float* __restrict__ C, const float* __restrict__ D,
                  const float* __restrict__ E, const float* __restrict__ F,
                  const float* __restrict__ G) {
    __shared__ float sV[2][DS][IO];
    __shared__ float sW2[DS][DS];
    __shared__ float sW1[IO][DS];
    const int tid = threadIdx.x;
    const int c = blockIdx.x, s = blockIdx.y, d = blockIdx.z;
    const int k0 = c * LCH;
    __half* Th = g_Th + (size_t)c * 256 * 320;
    __half* Tl = g_Tl + (size_t)c * 256 * 320;

    const float* src0 = ((d == 0) ? B : F) + (size_t)(k0 + s) * 512;
    for (int e = tid; e < 512; e += 128) sV[0][e >> 4][e & 15] = src0[e];
    if (d == 0) {
        const float* Ds = D + (size_t)(k0 + s) * 256;
        for (int e = tid; e < 256; e += 128) {
            const int o = e >> 4, i = e & 15;
            __half h, l; split_f16(Ds[o * 16 + i], h, l);
            const size_t idx = (size_t)(s * 16 + o) * 320 + s * 16 + i;
            Th[idx] = h; Tl[idx] = l;
        }
    }
    __syncthreads();

    int pb = 0;
    const int nsteps = (d == 0) ? (LCH - 1 - s) : s;
    for (int step = 0; step < nsteps; ++step) {
        const int t = (d == 0) ? (s + 1 + step) : (s - 1 - step);
        const int k = k0 + t;
        const float* W2 = ((d == 0) ? A : E) + (size_t)k * 1024;
        const float* W1 = ((d == 0) ? C : G) + (size_t)k * 512;
        for (int e = tid; e < 1024; e += 128) sW2[e >> 5][e & 31] = W2[e];
        for (int e = tid; e < 512;  e += 128) sW1[e >> 5][e & 31] = W1[e];
        __syncthreads();
        for (int e = tid; e < 256; e += 128) {
            const int o = e >> 4, i = e & 15;
            float acc = 0.f;
#pragma unroll
            for (int l = 0; l < DS; ++l) acc += sW1[o][l] * sV[pb][l][i];
            __half h, l2; split_f16(acc, h, l2);
            const size_t idx = (size_t)(t * 16 + o) * 320 + s * 16 + i;
            Th[idx] = h; Tl[idx] = l2;
        }
        for (int e = tid; e < 512; e += 128) {
            const int j = e >> 4, i = e & 15;
            float acc = 0.f;
#pragma unroll
            for (int l = 0; l < DS; ++l) acc += sW2[j][l] * sV[pb][l][i];
            sV[pb ^ 1][j][i] = acc;
        }
        __syncthreads();
        pb ^= 1;
    }
    for (int e = tid; e < 512; e += 128) {
        const int j = e >> 4, i = e & 15;
        __half h, l; split_f16(sV[pb][j][i], h, l);
        const size_t idx = (size_t)c * 64 * 256 + (size_t)(d * 32 + j) * 256 + s * 16 + i;
        g_Sh[idx] = h; g_Sl[idx] = l;
    }
}

// =====================================================================
// 3. M/N correction rows of T^T + propagators
// =====================================================================
__global__ __launch_bounds__(256)
void mn_kernel(const float* __restrict__ A, const float* __restrict__ C,
               const float* __restrict__ E, const float* __restrict__ G) {
    __shared__ float sV[2][DS][DS];
    __shared__ float sW2[DS][DS];
    __shared__ float sW1[IO][DS];
    const int tid = threadIdx.x;
    const int c = blockIdx.x, d = blockIdx.y;
    const int k0 = c * LCH;
    __half* Th = g_Th + (size_t)c * 256 * 320;
    __half* Tl = g_Tl + (size_t)c * 256 * 320;

    for (int e = tid; e < 1024; e += 256)
        sV[0][e >> 5][e & 31] = ((e >> 5) == (e & 31)) ? 1.f : 0.f;
    __syncthreads();

    int pb = 0;
    for (int step = 0; step < LCH; ++step) {
        const int t = (d == 0) ? step : (LCH - 1 - step);
        const int k = k0 + t;
        const float* W2 = ((d == 0) ? A : E) + (size_t)k * 1024;
        const float* W1 = ((d == 0) ? C : G) + (size_t)k * 512;
        for (int e = tid; e < 1024; e += 256) sW2[e >> 5][e & 31] = W2[e];
        for (int e = tid; e < 512;  e += 256) sW1[e >> 5][e & 31] = W1[e];
        __syncthreads();
        for (int e = tid; e < 512; e += 256) {
            const int o = e >> 5, j = e & 31;
            float acc = 0.f;
#pragma unroll
            for (int l = 0; l < DS; ++l) acc += sW1[o][l] * sV[pb][l][j];
            __half h, l2; split_f16(acc, h, l2);
            const size_t idx = (size_t)(t * 16 + o) * 320 + 256 + d * 32 + j;
            Th[idx] = h; Tl[idx] = l2;
        }
        for (int e = tid; e < 1024; e += 256) {
            const int i = e >> 5, j = e & 31;
            float acc = 0.f;
#pragma unroll
            for (int l = 0; l < DS; ++l) acc += sW2[i][l] * sV[pb][l][j];
            sV[pb ^ 1][i][j] = acc;
        }
        __syncthreads();
        pb ^= 1;
    }
    for (int e = tid; e < 1024; e += 256) {
        const int i = e >> 5, j = e & 31;
        g_P2[(size_t)(d * NCH + c) * 1024 + j * 32 + i] = sV[pb][i][j];
    }
}

// =====================================================================
// 4. GEMM1 (fp16 2-term): xloc[128x64] = U[128x256] x S^T
//    stage 32KB = A 16K | Bh 8K | Bl 8K; 2 stages (64KB -> 3 CTAs/SM)
//    128 thr = 4 warps (2m x 2n), warp tile 64x32     [R12 config, 28us]
// =====================================================================
#define G1S 32768
__global__ __launch_bounds__(128)
void gemm1_kernel() {
    extern __shared__ char smem[];
    const uint32_t sb = (uint32_t)__cvta_generic_to_shared(smem);
    const int tid = threadIdx.x, wid = tid >> 5, lane = tid & 31;
    const int mt = blockIdx.x, c = blockIdx.y;
    const int row0 = mt * 128;
    const int wm = wid & 1, wn = wid >> 1;
    const int mbase = wm * 64, nbase = wn * 32;

    auto load_stage = [&](int st, int kt) {
        char* base = smem + st * G1S;
#pragma unroll
        for (int q = 0; q < 8; ++q) {
            const int i = tid + 128 * q, r = i >> 3, k8 = i & 7;
            cpasync16(base + swz(r, k8),
                      g_Uh + (size_t)(row0 + r) * PTOT + c * 256 + kt * 64 + k8 * 8);
        }
#pragma unroll
        for (int q = 0; q < 4; ++q) {
            const int i = tid + 128 * q, r = i >> 3, k8 = i & 7;
            const uint32_t o = swz(r, k8);
            const size_t g = (size_t)c * 64 * 256 + (size_t)r * 256 + kt * 64 + k8 * 8;
            cpasync16(base + 16384 + o, g_Sh + g);
            cpasync16(base + 24576 + o, g_Sl + g);
        }
    };

    float acc[4][4][4];
#pragma unroll
    for (int mi = 0; mi < 4; ++mi)
#pragma unroll
        for (int ni = 0; ni < 4; ++ni)
#pragma unroll
            for (int q = 0; q < 4; ++q) acc[mi][ni][q] = 0.f;

    load_stage(0, 0); cpcommit();
    load_stage(1, 1); cpcommit();

    const int atile = lane >> 3;
    const int ar_off = (lane & 7) + (atile & 1) * 8;
    const int ak_off = atile >> 1;
    const int btt = lane & 15;
    const int br_off = btt & 7;
    const int bk_off = btt >> 3;

#pragma unroll 1
    for (int kt = 0; kt < 4; ++kt) {
        const int st = kt & 1;
        cpwait<1>(); __syncthreads();
        const uint32_t tb = sb + st * G1S;
#pragma unroll
        for (int ks = 0; ks < 4; ++ks) {
            uint32_t bh[4][2], bl[4][2];
#pragma unroll
            for (int ni = 0; ni < 4; ++ni) {
                const int r = nbase + ni * 8 + br_off;
                const uint32_t o = swz(r, 2 * ks + bk_off);
                ldmx2(bh[ni], tb + 16384 + o);
                ldmx2(bl[ni], tb + 24576 + o);
            }
#pragma unroll
            for (int mi = 0; mi < 4; ++mi) {
                const int r = mbase + mi * 16 + ar_off;
                uint32_t ah[4];
                ldmx4(ah, tb + swz(r, 2 * ks + ak_off));
#pragma unroll
                for (int ni = 0; ni < 4; ++ni) {
                    mma16816(acc[mi][ni], ah, bh[ni]);
                    mma16816(acc[mi][ni], ah, bl[ni]);
                }
            }
        }
        __syncthreads();
        if (kt < 2) load_stage(st, kt + 2);
        cpcommit();
    }

    // epilogue -> g_xloc [row][c][64]
#pragma unroll
    for (int mi = 0; mi < 4; ++mi) {
        const int r0 = row0 + mbase + mi * 16 + (lane >> 2);
#pragma unroll
        for (int ni = 0; ni < 4; ++ni) {
            const int n = nbase + ni * 8 + (lane & 3) * 2;
            float* d0 = g_xloc + ((size_t)r0 * NCH + c) * 64 + n;
            float* d1 = g_xloc + ((size_t)(r0 + 8) * NCH + c) * 64 + n;
            *(float2*)d0 = make_float2(acc[mi][ni][0], acc[mi][ni][1]);
            *(float2*)d1 = make_float2(acc[mi][ni][2], acc[mi][ni][3]);
        }
    }
}

// =====================================================================
// 5. Phase B: all 32 P matrices resident in smem, xloc prefetched.
//    Emits xin as fp16 (h only).
// =====================================================================
#define PB_T 128
__global__ __launch_bounds__(PB_T)
void phaseB_kernel() {
    extern __shared__ float sP[];   // [32][1024] in processing order
    const int tid = threadIdx.x;
    const int d = blockIdx.y;
    const int row = blockIdx.x * PB_T + tid;

    for (int q = tid; q < 32 * 256; q += PB_T) {
        const int ci = q >> 8;
        const int c = d ? (NCH - 1 - ci) : ci;
        ((float4*)sP)[q] = ((const float4*)(g_P2 + (size_t)(d * NCH + c) * 1024))[q & 255];
    }
    __syncthreads();

    ull xp[16];
#pragma unroll
    for (int ip = 0; ip < 16; ++ip) xp[ip] = 0;

    float4 xl[8];
    auto ldxloc = [&](int ci) {
        const int c = d ? (NCH - 1 - ci) : ci;
        const float4* p = (const float4*)(g_xloc + ((size_t)row * NCH + c) * 64 + d * 32);
#pragma unroll
        for (int q = 0; q < 8; ++q) xl[q] = p[q];
    };
    ldxloc(0);

#pragma unroll 1
    for (int ci = 0; ci < NCH; ++ci) {
        const int c = d ? (NCH - 1 - ci) : ci;
        const size_t xoff = ((size_t)row * NCH + c) * 64 + d * 32;

        ull acc[16];
#pragma unroll
        for (int q = 0; q < 8; ++q) {
            acc[2 * q]     = pack2(xl[q].x, xl[q].y);
            acc[2 * q + 1] = pack2(xl[q].z, xl[q].w);
        }
        if (ci + 1 < NCH) ldxloc(ci + 1);

#pragma unroll
        for (int ip = 0; ip < 16; ++ip) {
            float x0, x1; unpack2(xp[ip], x0, x1);
            ((__half2*)(g_xinh + xoff))[ip] =
                __halves2half2(__float2half_rn(x0), __float2half_rn(x1));

            const ull xx0 = dup2(x0), xx1 = dup2(x1);
            const ulonglong2* pr0 = (const ulonglong2*)&sP[ci * 1024 + (2 * ip) * DS];
            const ulonglong2* pr1 = (const ulonglong2*)&sP[ci * 1024 + (2 * ip + 1) * DS];
#pragma unroll
            for (int t = 0; t < 8; ++t) {
                const ulonglong2 p0 = pr0[t];
                acc[2 * t]     = fma2(p0.x, xx0, acc[2 * t]);
                acc[2 * t + 1] = fma2(p0.y, xx0, acc[2 * t + 1]);
            }
#pragma unroll
            for (int t = 0; t < 8; ++t) {
                const ulonglong2 p1 = pr1[t];
                acc[2 * t]     = fma2(p1.x, xx1, acc[2 * t]);
                acc[2 * t + 1] = fma2(p1.y, xx1, acc[2 * t + 1]);
            }
        }
#pragma unroll
        for (int ip = 0; ip < 16; ++ip) xp[ip] = acc[ip];
    }
}

// =====================================================================
// 6. GEMM2 (fp16 2-term): out[128x128] = A[128x320] x T^T + bias
//    N split in 2 per chunk. 256 thr = 8 warps (2m x 4n), warp tile 64x32.
//    stage 48KB = A 16K | Bh 16K | Bl 16K; 2 stages (96KB -> 2 CTAs/SM)
// =====================================================================
#define G2S 49152
__global__ __launch_bounds__(256)
void gemm2_kernel(const float* __restrict__ bias, float* __restrict__ out) {
    extern __shared__ char smem[];
    const uint32_t sb = (uint32_t)__cvta_generic_to_shared(smem);
    const int tid = threadIdx.x, wid = tid >> 5, lane = tid & 31;
    const int mt = blockIdx.x, nt = blockIdx.y, c = blockIdx.z;
    const int row0 = mt * 128, nc = nt * 128;
    const int wm = wid & 1, wn = wid >> 1;
    const int mbase = wm * 64, nbase = wn * 32;

    auto load_stage = [&](int st, int kt) {
        char* base = smem + st * G2S;
#pragma unroll
        for (int q = 0; q < 4; ++q) {
            const int i = tid + 256 * q, r = i >> 3, k8 = i & 7;
            const __half* src = (kt < 4)
                ? g_Uh + (size_t)(row0 + r) * PTOT + c * 256 + kt * 64 + k8 * 8
                : g_xinh + ((size_t)(row0 + r) * NCH + c) * 64 + k8 * 8;
            cpasync16(base + swz(r, k8), src);
        }
#pragma unroll
        for (int q = 0; q < 4; ++q) {
            const int i = tid + 256 * q, r = i >> 3, k8 = i & 7;
            const uint32_t o = swz(r, k8);
            const size_t g = (size_t)c * 256 * 320 + (size_t)(nc + r) * 320 + kt * 64 + k8 * 8;
            cpasync16(base + 16384 + o, g_Th + g);
            cpasync16(base + 32768 + o, g_Tl + g);
        }
    };

    float acc[4][4][4];
#pragma unroll
    for (int mi = 0; mi < 4; ++mi)
#pragma unroll
        for (int ni = 0; ni < 4; ++ni)
#pragma unroll
            for (int q = 0; q < 4; ++q) acc[mi][ni][q] = 0.f;

    load_stage(0, 0); cpcommit();
    load_stage(1, 1); cpcommit();

    const int atile = lane >> 3;
    const int ar_off = (lane & 7) + (atile & 1) * 8;
    const int ak_off = atile >> 1;
    const int btt = lane & 15;
    const int br_off = btt & 7;
    const int bk_off = btt >> 3;

#pragma unroll 1
    for (int kt = 0; kt < 5; ++kt) {
        const int st = kt & 1;
        cpwait<1>(); __syncthreads();
        const uint32_t tb = sb + st * G2S;
#pragma unroll
        for (int ks = 0; ks < 4; ++ks) {
            uint32_t bh[4][2], bl[4][2];
#pragma unroll
            for (int ni = 0; ni < 4; ++ni) {
                const int r = nbase + ni * 8 + br_off;
                const uint32_t o = swz(r, 2 * ks + bk_off);
                ldmx2(bh[ni], tb + 16384 + o);
                ldmx2(bl[ni], tb + 32768 + o);
            }
#pragma unroll
            for (int mi = 0; mi < 4; ++mi) {
                const int r = mbase + mi * 16 + ar_off;
                uint32_t ah[4];
                ldmx4(ah, tb + swz(r, 2 * ks + ak_off));
#pragma unroll
                for (int ni = 0; ni < 4; ++ni) {
                    mma16816(acc[mi][ni], ah, bh[ni]);
                    mma16816(acc[mi][ni], ah, bl[ni]);
                }
            }
        }
        __syncthreads();
        if (kt < 3) load_stage(st, kt + 2);
        cpcommit();
    }

    // epilogue: + bias, store float2 per tile-row
#pragma unroll
    for (int mi = 0; mi < 4; ++mi) {
        const int r0 = row0 + mbase + mi * 16 + (lane >> 2);
#pragma unroll
        for (int ni = 0; ni < 4; ++ni) {
            const int n = nc + nbase + ni * 8 + (lane & 3) * 2;
            const float2 bv = *(const float2*)(bias + c * 256 + n);
            float* d0 = out + (size_t)r0 * PTOT + c * 256 + n;
            float* d1 = out + (size_t)(r0 + 8) * PTOT + c * 256 + n;
            *(float2*)d0 = make_float2(acc[mi][ni][0] + bv.x, acc[mi][ni][1] + bv.y);
            *(float2*)d1 = make_float2(acc[mi][ni][2] + bv.x, acc[mi][ni][3] + bv.y);
        }
    }
}

// =====================================================================
extern "C" void kernel_launch(void* const* d_in, const int* in_sizes, int n_in,
                              void* d_out, int out_size) {
    const float* U    = (const float*)d_in[0];
    const float* A    = (const float*)d_in[1];
    const float* B    = (const float*)d_in[2];
    const float* C    = (const float*)d_in[3];
    const float* D    = (const float*)d_in[4];
    const float* E    = (const float*)d_in[5];
    const float* F    = (const float*)d_in[6];
    const float* G    = (const float*)d_in[7];
    const float* bias = (const float*)d_in[8];
    float* out = (float*)d_out;

    cudaFuncSetAttribute(gemm1_kernel, cudaFuncAttributeMaxDynamicSharedMemorySize, 2 * G1S);
    cudaFuncSetAttribute(gemm2_kernel, cudaFuncAttributeMaxDynamicSharedMemorySize, 2 * G2S);
    cudaFuncSetAttribute(phaseB_kernel, cudaFuncAttributeMaxDynamicSharedMemorySize, 32 * 1024 * 4);

    convertU_kernel<<<(BATCH * PTOT / 4) / 256, 256>>>(U);
    strip_kernel<<<dim3(NCH, LCH, 2), 128>>>(A, B, C, D, E, F, G);
    mn_kernel<<<dim3(NCH, 2), 256>>>(A, C, E, G);
    gemm1_kernel<<<dim3(BATCH / 128, NCH), 128, 2 * G1S>>>();
    phaseB_kernel<<<dim3(BATCH / PB_T, 2), PB_T, 32 * 1024 * 4>>>();
    gemm2_kernel<<<dim3(BATCH / 128, 2, NCH), 256, 2 * G2S>>>(bias, out);
}

// round 14
// speedup vs baseline: 1.1703x; 1.1703x over previous
#include <cuda_runtime.h>
#include <cuda_fp16.h>
#include <cstdint>

#define BATCH 4096
#define NST   512
#define IO    16
#define DS    32
#define PTOT  8192
#define NCH   32
#define LCH   16

typedef unsigned long long ull;

// ---------------- device scratch (static; no mallocs) ----------------
__device__ __align__(16) __half g_Uh[(size_t)BATCH * PTOT];            // fp16(U)
__device__ __align__(16) __half g_Th[(size_t)NCH * 256 * 320];         // T^T per chunk [n][k]
__device__ __align__(16) __half g_Tl[(size_t)NCH * 256 * 320];
__device__ __align__(16) __half g_Sh[(size_t)NCH * 64 * 256];          // S^T per chunk [n][k]
__device__ __align__(16) __half g_Sl[(size_t)NCH * 64 * 256];
__device__ __align__(16) float g_xloc[(size_t)BATCH * NCH * 64];       // [row][c][64]
__device__ __align__(16) __half g_xinh[(size_t)BATCH * NCH * 64];      // fp16(xin)
__device__ float g_P2[2 * NCH * DS * DS];

// ---------------- f32x2 helpers ----------------
__device__ __forceinline__ ull pack2(float lo, float hi) {
    ull r; asm("mov.b64 %0, {%1, %2};" : "=l"(r) : "f"(lo), "f"(hi)); return r;
}
__device__ __forceinline__ ull dup2(float v) { return pack2(v, v); }
__device__ __forceinline__ void unpack2(ull p, float& lo, float& hi) {
    asm("mov.b64 {%0, %1}, %2;" : "=f"(lo), "=f"(hi) : "l"(p));
}
__device__ __forceinline__ ull fma2(ull a, ull b, ull c) {
    ull r; asm("fma.rn.f32x2 %0, %1, %2, %3;" : "=l"(r) : "l"(a), "l"(b), "l"(c)); return r;
}

// ---------------- cp.async helpers ----------------
__device__ __forceinline__ void cpasync16(void* s, const void* g) {
    uint32_t sa = (uint32_t)__cvta_generic_to_shared(s);
    asm volatile("cp.async.cg.shared.global [%0], [%1], 16;" :: "r"(sa), "l"(g));
}
__device__ __forceinline__ void cpcommit() { asm volatile("cp.async.commit_group;"); }
template<int N> __device__ __forceinline__ void cpwait() {
    asm volatile("cp.async.wait_group %0;" :: "n"(N));
}

// ---------------- mma.sync / ldmatrix helpers (fp16) ----------------
__device__ __forceinline__ void ldmx4(uint32_t* r, uint32_t addr) {
    asm volatile("ldmatrix.sync.aligned.m8n8.x4.shared.b16 {%0,%1,%2,%3}, [%4];"
        : "=r"(r[0]), "=r"(r[1]), "=r"(r[2]), "=r"(r[3]) : "r"(addr));
}
__device__ __forceinline__ void ldmx2(uint32_t* r, uint32_t addr) {
    asm volatile("ldmatrix.sync.aligned.m8n8.x2.shared.b16 {%0,%1}, [%2];"
        : "=r"(r[0]), "=r"(r[1]) : "r"(addr));
}
__device__ __forceinline__ void mma16816(float* c, const uint32_t* a, const uint32_t* b) {
    asm volatile(
        "mma.sync.aligned.m16n8k16.row.col.f32.f16.f16.f32 "
        "{%0,%1,%2,%3}, {%4,%5,%6,%7}, {%8,%9}, {%0,%1,%2,%3};"
        : "+f"(c[0]), "+f"(c[1]), "+f"(c[2]), "+f"(c[3])
        : "r"(a[0]), "r"(a[1]), "r"(a[2]), "r"(a[3]), "r"(b[0]), "r"(b[1]));
}
// swizzled smem offset: logical (row r, 16B chunk k8) in a [*,64]fp16 tile
__device__ __forceinline__ uint32_t swz(int r, int k8) {
    return (uint32_t)(r * 128 + ((k8 ^ (r & 7)) << 4));
}

__device__ __forceinline__ void split_f16(float v, __half& h, __half& l) {
    h = __float2half_rn(v);
    l = __float2half_rn(v - __half2float(h));
}

// =====================================================================
// 1. Convert U -> fp16 (single array)
// =====================================================================
__global__ __launch_bounds__(256)
void convertU_kernel(const float* __restrict__ U) {
    const size_t i = (size_t)blockIdx.x * 256 + threadIdx.x;
    const float4 v = ((const float4*)U)[i];
    ((__half2*)g_Uh)[2*i]   = __halves2half2(__float2half_rn(v.x), __float2half_rn(v.y));
    ((__half2*)g_Uh)[2*i+1] = __halves2half2(__float2half_rn(v.z), __float2half_rn(v.w));
}

// =====================================================================
// 2. Strip precompute -> T^T (fp16 h/l) input blocks + S^T columns
// =====================================================================
__global__ __launch_bounds__(128)
void strip_kernel(const float* __restrict__ A, const float* __restrict__ B,
                  const float* __restrict__ C, const float* __restrict__ D,
                  const float* __restrict__ E, const float* __restrict__ F,
                  const float* __restrict__ G) {
    __shared__ float sV[2][DS][IO];
    __shared__ float sW2[DS][DS];
    __shared__ float sW1[IO][DS];
    const int tid = threadIdx.x;
    const int c = blockIdx.x, s = blockIdx.y, d = blockIdx.z;
    const int k0 = c * LCH;
    __half* Th = g_Th + (size_t)c * 256 * 320;
    __half* Tl = g_Tl + (size_t)c * 256 * 320;

    const float* src0 = ((d == 0) ? B : F) + (size_t)(k0 + s) * 512;
    for (int e = tid; e < 512; e += 128) sV[0][e >> 4][e & 15] = src0[e];
    if (d == 0) {
        const float* Ds = D + (size_t)(k0 + s) * 256;
        for (int e = tid; e < 256; e += 128) {
            const int o = e >> 4, i = e & 15;
            __half h, l; split_f16(Ds[o * 16 + i], h, l);
            const size_t idx = (size_t)(s * 16 + o) * 320 + s * 16 + i;
            Th[idx] = h; Tl[idx] = l;
        }
    }
    __syncthreads();

    int pb = 0;
    const int nsteps = (d == 0) ? (LCH - 1 - s) : s;
    for (int step = 0; step < nsteps; ++step) {
        const int t = (d == 0) ? (s + 1 + step) : (s - 1 - step);
        const int k = k0 + t;
        const float* W2 = ((d == 0) ? A : E) + (size_t)k * 1024;
        const float* W1 = ((d == 0) ? C : G) + (size_t)k * 512;
        for (int e = tid; e < 1024; e += 128) sW2[e >> 5][e & 31] = W2[e];
        for (int e = tid; e < 512;  e += 128) sW1[e >> 5][e & 31] = W1[e];
        __syncthreads();
        for (int e = tid; e < 256; e += 128) {
            const int o = e >> 4, i = e & 15;
            float acc = 0.f;
#pragma unroll
            for (int l = 0; l < DS; ++l) acc += sW1[o][l] * sV[pb][l][i];
            __half h, l2; split_f16(acc, h, l2);
            const size_t idx = (size_t)(t * 16 + o) * 320 + s * 16 + i;
            Th[idx] = h; Tl[idx] = l2;
        }
        for (int e = tid; e < 512; e += 128) {
            const int j = e >> 4, i = e & 15;
            float acc = 0.f;
#pragma unroll
            for (int l = 0; l < DS; ++l) acc += sW2[j][l] * sV[pb][l][i];
            sV[pb ^ 1][j][i] = acc;
        }
        __syncthreads();
        pb ^= 1;
    }
    for (int e = tid; e < 512; e += 128) {
        const int j = e >> 4, i = e & 15;
        __half h, l; split_f16(sV[pb][j][i], h, l);
        const size_t idx = (size_t)c * 64 * 256 + (size_t)(d * 32 + j) * 256 + s * 16 + i;
        g_Sh[idx] = h; g_Sl[idx] = l;
    }
}

// =====================================================================
// 3. M/N correction rows of T^T + propagators
// =====================================================================
__global__ __launch_bounds__(256)
void mn_kernel(const float* __restrict__ A, const float* __restrict__ C,
               const float* __restrict__ E, const float* __restrict__ G) {
    __shared__ float sV[2][DS][DS];
    __shared__ float sW2[DS][DS];
    __shared__ float sW1[IO][DS];
    const int tid = threadIdx.x;
    const int c = blockIdx.x, d = blockIdx.y;
    const int k0 = c * LCH;
    __half* Th = g_Th + (size_t)c * 256 * 320;
    __half* Tl = g_Tl + (size_t)c * 256 * 320;

    for (int e = tid; e < 1024; e += 256)
        sV[0][e >> 5][e & 31] = ((e >> 5) == (e & 31)) ? 1.f : 0.f;
    __syncthreads();

    int pb = 0;
    for (int step = 0; step < LCH; ++step) {
        const int t = (d == 0) ? step : (LCH - 1 - step);
        const int k = k0 + t;
        const float* W2 = ((d == 0) ? A : E) + (size_t)k * 1024;
        const float* W1 = ((d == 0) ? C : G) + (size_t)k * 512;
        for (int e = tid; e < 1024; e += 256) sW2[e >> 5][e & 31] = W2[e];
        for (int e = tid; e < 512;  e += 256) sW1[e >> 5][e & 31] = W1[e];
        __syncthreads();
        for (int e = tid; e < 512; e += 256) {
            const int o = e >> 5, j = e & 31;
            float acc = 0.f;
#pragma unroll
            for (int l = 0; l < DS; ++l) acc += sW1[o][l] * sV[pb][l][j];
            __half h, l2; split_f16(acc, h, l2);
            const size_t idx = (size_t)(t * 16 + o) * 320 + 256 + d * 32 + j;
            Th[idx] = h; Tl[idx] = l2;
        }
        for (int e = tid; e < 1024; e += 256) {
            const int i = e >> 5, j = e & 31;
            float acc = 0.f;
#pragma unroll
            for (int l = 0; l < DS; ++l) acc += sW2[i][l] * sV[pb][l][j];
            sV[pb ^ 1][i][j] = acc;
        }
        __syncthreads();
        pb ^= 1;
    }
    for (int e = tid; e < 1024; e += 256) {
        const int i = e >> 5, j = e & 31;
        g_P2[(size_t)(d * NCH + c) * 1024 + j * 32 + i] = sV[pb][i][j];
    }
}

// =====================================================================
// 4. GEMM1 (fp16 2-term): xloc[128x64] = U[128x256] x S^T
//    stage 32KB = A 16K | Bh 8K | Bl 8K; 2 stages (64KB)
//    128 thr = 4 warps (2m x 2n), warp tile 64x32     [R12 config, 28us]
// =====================================================================
#define G1S 32768
__global__ __launch_bounds__(128)
void gemm1_kernel() {
    extern __shared__ char smem[];
    const uint32_t sb = (uint32_t)__cvta_generic_to_shared(smem);
    const int tid = threadIdx.x, wid = tid >> 5, lane = tid & 31;
    const int mt = blockIdx.x, c = blockIdx.y;
    const int row0 = mt * 128;
    const int wm = wid & 1, wn = wid >> 1;
    const int mbase = wm * 64, nbase = wn * 32;

    auto load_stage = [&](int st, int kt) {
        char* base = smem + st * G1S;
#pragma unroll
        for (int q = 0; q < 8; ++q) {
            const int i = tid + 128 * q, r = i >> 3, k8 = i & 7;
            cpasync16(base + swz(r, k8),
                      g_Uh + (size_t)(row0 + r) * PTOT + c * 256 + kt * 64 + k8 * 8);
        }
#pragma unroll
        for (int q = 0; q < 4; ++q) {
            const int i = tid + 128 * q, r = i >> 3, k8 = i & 7;
            const uint32_t o = swz(r, k8);
            const size_t g = (size_t)c * 64 * 256 + (size_t)r * 256 + kt * 64 + k8 * 8;
            cpasync16(base + 16384 + o, g_Sh + g);
            cpasync16(base + 24576 + o, g_Sl + g);
        }
    };

    float acc[4][4][4];
#pragma unroll
    for (int mi = 0; mi < 4; ++mi)
#pragma unroll
        for (int ni = 0; ni < 4; ++ni)
#pragma unroll
            for (int q = 0; q < 4; ++q) acc[mi][ni][q] = 0.f;

    load_stage(0, 0); cpcommit();
    load_stage(1, 1); cpcommit();

    const int atile = lane >> 3;
    const int ar_off = (lane & 7) + (atile & 1) * 8;
    const int ak_off = atile >> 1;
    const int btt = lane & 15;
    const int br_off = btt & 7;
    const int bk_off = btt >> 3;

#pragma unroll 1
    for (int kt = 0; kt < 4; ++kt) {
        const int st = kt & 1;
        cpwait<1>(); __syncthreads();
        const uint32_t tb = sb + st * G1S;
#pragma unroll
        for (int ks = 0; ks < 4; ++ks) {
            uint32_t bh[4][2], bl[4][2];
#pragma unroll
            for (int ni = 0; ni < 4; ++ni) {
                const int r = nbase + ni * 8 + br_off;
                const uint32_t o = swz(r, 2 * ks + bk_off);
                ldmx2(bh[ni], tb + 16384 + o);
                ldmx2(bl[ni], tb + 24576 + o);
            }
#pragma unroll
            for (int mi = 0; mi < 4; ++mi) {
                const int r = mbase + mi * 16 + ar_off;
                uint32_t ah[4];
                ldmx4(ah, tb + swz(r, 2 * ks + ak_off));
#pragma unroll
                for (int ni = 0; ni < 4; ++ni) {
                    mma16816(acc[mi][ni], ah, bh[ni]);
                    mma16816(acc[mi][ni], ah, bl[ni]);
                }
            }
        }
        __syncthreads();
        if (kt < 2) load_stage(st, kt + 2);
        cpcommit();
    }

    // epilogue -> g_xloc [row][c][64]
#pragma unroll
    for (int mi = 0; mi < 4; ++mi) {
        const int r0 = row0 + mbase + mi * 16 + (lane >> 2);
#pragma unroll
        for (int ni = 0; ni < 4; ++ni) {
            const int n = nbase + ni * 8 + (lane & 3) * 2;
            float* d0 = g_xloc + ((size_t)r0 * NCH + c) * 64 + n;
            float* d1 = g_xloc + ((size_t)(r0 + 8) * NCH + c) * 64 + n;
            *(float2*)d0 = make_float2(acc[mi][ni][0], acc[mi][ni][1]);
            *(float2*)d1 = make_float2(acc[mi][ni][2], acc[mi][ni][3]);
        }
    }
}

// =====================================================================
// 5. Phase B: all 32 P matrices resident in smem, xloc prefetched.
//    Emits xin as fp16 (h only).
// =====================================================================
#define PB_T 128
__global__ __launch_bounds__(PB_T)
void phaseB_kernel() {
    extern __shared__ float sP[];   // [32][1024] in processing order
    const int tid = threadIdx.x;
    const int d = blockIdx.y;
    const int row = blockIdx.x * PB_T + tid;

    for (int q = tid; q < 32 * 256; q += PB_T) {
        const int ci = q >> 8;
        const int c = d ? (NCH - 1 - ci) : ci;
        ((float4*)sP)[q] = ((const float4*)(g_P2 + (size_t)(d * NCH + c) * 1024))[q & 255];
    }
    __syncthreads();

    ull xp[16];
#pragma unroll
    for (int ip = 0; ip < 16; ++ip) xp[ip] = 0;

    float4 xl[8];
    auto ldxloc = [&](int ci) {
        const int c = d ? (NCH - 1 - ci) : ci;
        const float4* p = (const float4*)(g_xloc + ((size_t)row * NCH + c) * 64 + d * 32);
#pragma unroll
        for (int q = 0; q < 8; ++q) xl[q] = p[q];
    };
    ldxloc(0);

#pragma unroll 1
    for (int ci = 0; ci < NCH; ++ci) {
        const int c = d ? (NCH - 1 - ci) : ci;
        const size_t xoff = ((size_t)row * NCH + c) * 64 + d * 32;

        ull acc[16];
#pragma unroll
        for (int q = 0; q < 8; ++q) {
            acc[2 * q]     = pack2(xl[q].x, xl[q].y);
            acc[2 * q + 1] = pack2(xl[q].z, xl[q].w);
        }
        if (ci + 1 < NCH) ldxloc(ci + 1);

#pragma unroll
        for (int ip = 0; ip < 16; ++ip) {
            float x0, x1; unpack2(xp[ip], x0, x1);
            ((__half2*)(g_xinh + xoff))[ip] =
                __halves2half2(__float2half_rn(x0), __float2half_rn(x1));

            const ull xx0 = dup2(x0), xx1 = dup2(x1);
            const ulonglong2* pr0 = (const ulonglong2*)&sP[ci * 1024 + (2 * ip) * DS];
            const ulonglong2* pr1 = (const ulonglong2*)&sP[ci * 1024 + (2 * ip + 1) * DS];
#pragma unroll
            for (int t = 0; t < 8; ++t) {
                const ulonglong2 p0 = pr0[t];
                acc[2 * t]     = fma2(p0.x, xx0, acc[2 * t]);
                acc[2 * t + 1] = fma2(p0.y, xx0, acc[2 * t + 1]);
            }
#pragma unroll
            for (int t = 0; t < 8; ++t) {
                const ulonglong2 p1 = pr1[t];
                acc[2 * t]     = fma2(p1.x, xx1, acc[2 * t]);
                acc[2 * t + 1] = fma2(p1.y, xx1, acc[2 * t + 1]);
            }
        }
#pragma unroll
        for (int ip = 0; ip < 16; ++ip) xp[ip] = acc[ip];
    }
}

// =====================================================================
// 6. GEMM2 (fp16 SINGLE-term): out[128x256] = A[128x320] x Th^T + bias
//    FULL N per CTA. 256 thr = 8 warps (2m x 4n), warp tile 64x64.
//    stage 48KB = A 16K | Bh 32K; 2 stages (96KB)
// =====================================================================
#define G2S 49152
__global__ __launch_bounds__(256)
void gemm2_kernel(const float* __restrict__ bias, float* __restrict__ out) {
    extern __shared__ char smem[];
    const uint32_t sb = (uint32_t)__cvta_generic_to_shared(smem);
    const int tid = threadIdx.x, wid = tid >> 5, lane = tid & 31;
    const int mt = blockIdx.x, c = blockIdx.y;
    const int row0 = mt * 128;
    const int wm = wid & 1, wn = wid >> 1;
    const int mbase = wm * 64, nbase = wn * 64;

    auto load_stage = [&](int st, int kt) {
        char* base = smem + st * G2S;
#pragma unroll
        for (int q = 0; q < 4; ++q) {
            const int i = tid + 256 * q, r = i >> 3, k8 = i & 7;
            const __half* src = (kt < 4)
                ? g_Uh + (size_t)(row0 + r) * PTOT + c * 256 + kt * 64 + k8 * 8
                : g_xinh + ((size_t)(row0 + r) * NCH + c) * 64 + k8 * 8;
            cpasync16(base + swz(r, k8), src);
        }
#pragma unroll
        for (int q = 0; q < 8; ++q) {
            const int i = tid + 256 * q, r = i >> 3, k8 = i & 7;
            const size_t g = (size_t)c * 256 * 320 + (size_t)r * 320 + kt * 64 + k8 * 8;
            cpasync16(base + 16384 + swz(r, k8), g_Th + g);
        }
    };

    float acc[4][8][4];
#pragma unroll
    for (int mi = 0; mi < 4; ++mi)
#pragma unroll
        for (int ni = 0; ni < 8; ++ni)
#pragma unroll
            for (int q = 0; q < 4; ++q) acc[mi][ni][q] = 0.f;

    load_stage(0, 0); cpcommit();
    load_stage(1, 1); cpcommit();

    const int atile = lane >> 3;
    const int ar_off = (lane & 7) + (atile & 1) * 8;
    const int ak_off = atile >> 1;
    const int btt = lane & 15;
    const int br_off = btt & 7;
    const int bk_off = btt >> 3;

#pragma unroll 1
    for (int kt = 0; kt < 5; ++kt) {
        const int st = kt & 1;
        cpwait<1>(); __syncthreads();
        const uint32_t tb = sb + st * G2S;
#pragma unroll
        for (int ks = 0; ks < 4; ++ks) {
            uint32_t bh[8][2];
#pragma unroll
            for (int ni = 0; ni < 8; ++ni) {
                const int r = nbase + ni * 8 + br_off;
                ldmx2(bh[ni], tb + 16384 + swz(r, 2 * ks + bk_off));
            }
#pragma unroll
            for (int mi = 0; mi < 4; ++mi) {
                const int r = mbase + mi * 16 + ar_off;
                uint32_t ah[4];
                ldmx4(ah, tb + swz(r, 2 * ks + ak_off));
#pragma unroll
                for (int ni = 0; ni < 8; ++ni)
                    mma16816(acc[mi][ni], ah, bh[ni]);
            }
        }
        __syncthreads();
        if (kt < 3) load_stage(st, kt + 2);
        cpcommit();
    }

    // epilogue: + bias, store float2 per tile-row
#pragma unroll
    for (int mi = 0; mi < 4; ++mi) {
        const int r0 = row0 + mbase + mi * 16 + (lane >> 2);
#pragma unroll
        for (int ni = 0; ni < 8; ++ni) {
            const int n = nbase + ni * 8 + (lane & 3) * 2;
            const float2 bv = *(const float2*)(bias + c * 256 + n);
            float* d0 = out + (size_t)r0 * PTOT + c * 256 + n;
            float* d1 = out + (size_t)(r0 + 8) * PTOT + c * 256 + n;
            *(float2*)d0 = make_float2(acc[mi][ni][0] + bv.x, acc[mi][ni][1] + bv.y);
            *(float2*)d1 = make_float2(acc[mi][ni][2] + bv.x, acc[mi][ni][3] + bv.y);
        }
    }
}

// =====================================================================
extern "C" void kernel_launch(void* const* d_in, const int* in_sizes, int n_in,
                              void* d_out, int out_size) {
    const float* U    = (const float*)d_in[0];
    const float* A    = (const float*)d_in[1];
    const float* B    = (const float*)d_in[2];
    const float* C    = (const float*)d_in[3];
    const float* D    = (const float*)d_in[4];
    const float* E    = (const float*)d_in[5];
    const float* F    = (const float*)d_in[6];
    const float* G    = (const float*)d_in[7];
    const float* bias = (const float*)d_in[8];
    float* out = (float*)d_out;

    cudaFuncSetAttribute(gemm1_kernel, cudaFuncAttributeMaxDynamicSharedMemorySize, 2 * G1S);
    cudaFuncSetAttribute(gemm2_kernel, cudaFuncAttributeMaxDynamicSharedMemorySize, 2 * G2S);
    cudaFuncSetAttribute(phaseB_kernel, cudaFuncAttributeMaxDynamicSharedMemorySize, 32 * 1024 * 4);

    convertU_kernel<<<(BATCH * PTOT / 4) / 256, 256>>>(U);
    strip_kernel<<<dim3(NCH, LCH, 2), 128>>>(A, B, C, D, E, F, G);
    mn_kernel<<<dim3(NCH, 2), 256>>>(A, C, E, G);
    gemm1_kernel<<<dim3(BATCH / 128, NCH), 128, 2 * G1S>>>();
    phaseB_kernel<<<dim3(BATCH / PB_T, 2), PB_T, 32 * 1024 * 4>>>();
    gemm2_kernel<<<dim3(BATCH / 128, NCH), 256, 2 * G2S>>>(bias, out);
}

// round 15
// speedup vs baseline: 1.1774x; 1.0061x over previous
#include <cuda_runtime.h>
#include <cuda_fp16.h>
#include <cstdint>

#define BATCH 4096
#define NST   512
#define IO    16
#define DS    32
#define PTOT  8192
#define NCH   32
#define LCH   16

typedef unsigned long long ull;

// ---------------- device scratch (static; no mallocs) ----------------
__device__ __align__(16) __half g_Uh[(size_t)BATCH * PTOT];            // fp16(U), written by gemm1
__device__ __align__(16) __half g_Th[(size_t)NCH * 256 * 320];         // T^T per chunk [n][k]
__device__ __align__(16) __half g_Sh[(size_t)NCH * 64 * 256];          // S^T per chunk [n][k]
__device__ __align__(16) float g_xloc[(size_t)BATCH * NCH * 64];       // [row][c][64]
__device__ __align__(16) __half g_xinh[(size_t)BATCH * NCH * 64];      // fp16(xin)
__device__ float g_P2[2 * NCH * DS * DS];

// ---------------- f32x2 helpers ----------------
__device__ __forceinline__ ull pack2(float lo, float hi) {
    ull r; asm("mov.b64 %0, {%1, %2};" : "=l"(r) : "f"(lo), "f"(hi)); return r;
}
__device__ __forceinline__ ull dup2(float v) { return pack2(v, v); }
__device__ __forceinline__ void unpack2(ull p, float& lo, float& hi) {
    asm("mov.b64 {%0, %1}, %2;" : "=f"(lo), "=f"(hi) : "l"(p));
}
__device__ __forceinline__ ull fma2(ull a, ull b, ull c) {
    ull r; asm("fma.rn.f32x2 %0, %1, %2, %3;" : "=l"(r) : "l"(a), "l"(b), "l"(c)); return r;
}

// ---------------- cp.async helpers ----------------
__device__ __forceinline__ void cpasync16(void* s, const void* g) {
    uint32_t sa = (uint32_t)__cvta_generic_to_shared(s);
    asm volatile("cp.async.cg.shared.global [%0], [%1], 16;" :: "r"(sa), "l"(g));
}
__device__ __forceinline__ void cpcommit() { asm volatile("cp.async.commit_group;"); }
template<int N> __device__ __forceinline__ void cpwait() {
    asm volatile("cp.async.wait_group %0;" :: "n"(N));
}

// ---------------- mma.sync / ldmatrix helpers (fp16) ----------------
__device__ __forceinline__ void ldmx4(uint32_t* r, uint32_t addr) {
    asm volatile("ldmatrix.sync.aligned.m8n8.x4.shared.b16 {%0,%1,%2,%3}, [%4];"
        : "=r"(r[0]), "=r"(r[1]), "=r"(r[2]), "=r"(r[3]) : "r"(addr));
}
__device__ __forceinline__ void ldmx2(uint32_t* r, uint32_t addr) {
    asm volatile("ldmatrix.sync.aligned.m8n8.x2.shared.b16 {%0,%1}, [%2];"
        : "=r"(r[0]), "=r"(r[1]) : "r"(addr));
}
__device__ __forceinline__ void mma16816(float* c, const uint32_t* a, const uint32_t* b) {
    asm volatile(
        "mma.sync.aligned.m16n8k16.row.col.f32.f16.f16.f32 "
        "{%0,%1,%2,%3}, {%4,%5,%6,%7}, {%8,%9}, {%0,%1,%2,%3};"
        : "+f"(c[0]), "+f"(c[1]), "+f"(c[2]), "+f"(c[3])
        : "r"(a[0]), "r"(a[1]), "r"(a[2]), "r"(a[3]), "r"(b[0]), "r"(b[1]));
}
// swizzled smem offset: logical (row r, 16B chunk k8) in a [*,64]fp16 tile
__device__ __forceinline__ uint32_t swz(int r, int k8) {
    return (uint32_t)(r * 128 + ((k8 ^ (r & 7)) << 4));
}
__device__ __forceinline__ uint32_t h2u(__half2 h) {
    uint32_t r; memcpy(&r, &h, 4); return r;
}

// =====================================================================
// 1. Strip precompute -> T^T (fp16) input blocks + S^T columns
// =====================================================================
__global__ __launch_bounds__(128)
void strip_kernel(const float* __restrict__ A, const float* __restrict__ B,
                  const float* __restrict__ C, const float* __restrict__ D,
                  const float* __restrict__ E, const float* __restrict__ F,
                  const float* __restrict__ G) {
    __shared__ float sV[2][DS][IO];
    __shared__ float sW2[DS][DS];
    __shared__ float sW1[IO][DS];
    const int tid = threadIdx.x;
    const int c = blockIdx.x, s = blockIdx.y, d = blockIdx.z;
    const int k0 = c * LCH;
    __half* Th = g_Th + (size_t)c * 256 * 320;

    const float* src0 = ((d == 0) ? B : F) + (size_t)(k0 + s) * 512;
    for (int e = tid; e < 512; e += 128) sV[0][e >> 4][e & 15] = src0[e];
    if (d == 0) {
        const float* Ds = D + (size_t)(k0 + s) * 256;
        for (int e = tid; e < 256; e += 128) {
            const int o = e >> 4, i = e & 15;
            Th[(size_t)(s * 16 + o) * 320 + s * 16 + i] = __float2half_rn(Ds[o * 16 + i]);
        }
    }
    __syncthreads();

    int pb = 0;
    const int nsteps = (d == 0) ? (LCH - 1 - s) : s;
    for (int step = 0; step < nsteps; ++step) {
        const int t = (d == 0) ? (s + 1 + step) : (s - 1 - step);
        const int k = k0 + t;
        const float* W2 = ((d == 0) ? A : E) + (size_t)k * 1024;
        const float* W1 = ((d == 0) ? C : G) + (size_t)k * 512;
        for (int e = tid; e < 1024; e += 128) sW2[e >> 5][e & 31] = W2[e];
        for (int e = tid; e < 512;  e += 128) sW1[e >> 5][e & 31] = W1[e];
        __syncthreads();
        for (int e = tid; e < 256; e += 128) {
            const int o = e >> 4, i = e & 15;
            float acc = 0.f;
#pragma unroll
            for (int l = 0; l < DS; ++l) acc += sW1[o][l] * sV[pb][l][i];
            Th[(size_t)(t * 16 + o) * 320 + s * 16 + i] = __float2half_rn(acc);
        }
        for (int e = tid; e < 512; e += 128) {
            const int j = e >> 4, i = e & 15;
            float acc = 0.f;
#pragma unroll
            for (int l = 0; l < DS; ++l) acc += sW2[j][l] * sV[pb][l][i];
            sV[pb ^ 1][j][i] = acc;
        }
        __syncthreads();
        pb ^= 1;
    }
    for (int e = tid; e < 512; e += 128) {
        const int j = e >> 4, i = e & 15;
        g_Sh[(size_t)c * 64 * 256 + (size_t)(d * 32 + j) * 256 + s * 16 + i] =
            __float2half_rn(sV[pb][j][i]);
    }
}

// =====================================================================
// 2. M/N correction rows of T^T + propagators
// =====================================================================
__global__ __launch_bounds__(256)
void mn_kernel(const float* __restrict__ A, const float* __restrict__ C,
               const float* __restrict__ E, const float* __restrict__ G) {
    __shared__ float sV[2][DS][DS];
    __shared__ float sW2[DS][DS];
    __shared__ float sW1[IO][DS];
    const int tid = threadIdx.x;
    const int c = blockIdx.x, d = blockIdx.y;
    const int k0 = c * LCH;
    __half* Th = g_Th + (size_t)c * 256 * 320;

    for (int e = tid; e < 1024; e += 256)
        sV[0][e >> 5][e & 31] = ((e >> 5) == (e & 31)) ? 1.f : 0.f;
    __syncthreads();

    int pb = 0;
    for (int step = 0; step < LCH; ++step) {
        const int t = (d == 0) ? step : (LCH - 1 - step);
        const int k = k0 + t;
        const float* W2 = ((d == 0) ? A : E) + (size_t)k * 1024;
        const float* W1 = ((d == 0) ? C : G) + (size_t)k * 512;
        for (int e = tid; e < 1024; e += 256) sW2[e >> 5][e & 31] = W2[e];
        for (int e = tid; e < 512;  e += 256) sW1[e >> 5][e & 31] = W1[e];
        __syncthreads();
        for (int e = tid; e < 512; e += 256) {
            const int o = e >> 5, j = e & 31;
            float acc = 0.f;
#pragma unroll
            for (int l = 0; l < DS; ++l) acc += sW1[o][l] * sV[pb][l][j];
            Th[(size_t)(t * 16 + o) * 320 + 256 + d * 32 + j] = __float2half_rn(acc);
        }
        for (int e = tid; e < 1024; e += 256) {
            const int i = e >> 5, j = e & 31;
            float acc = 0.f;
#pragma unroll
            for (int l = 0; l < DS; ++l) acc += sW2[i][l] * sV[pb][l][j];
            sV[pb ^ 1][i][j] = acc;
        }
        __syncthreads();
        pb ^= 1;
    }
    for (int e = tid; e < 1024; e += 256) {
        const int i = e >> 5, j = e & 31;
        g_P2[(size_t)(d * NCH + c) * 1024 + j * 32 + i] = sV[pb][i][j];
    }
}

// =====================================================================
// 3. GEMM1 (fp16 single-term, fused U-convert):
//    xloc[128x64] = fp16(U)[128x256] x Sh^T ; also writes g_Uh.
//    stage 58KB = Af32 34816(pad 272B/row) | Ah 16K | Bh 8K; 2 stages.
//    128 thr = 4 warps (2m x 2n), warp tile 64x32.
// =====================================================================
#define G1S 59392
#define AH_OFF 34816
#define BH_OFF 51200
__global__ __launch_bounds__(128)
void gemm1_kernel(const float* __restrict__ U) {
    extern __shared__ char smem[];
    const uint32_t sb = (uint32_t)__cvta_generic_to_shared(smem);
    const int tid = threadIdx.x, wid = tid >> 5, lane = tid & 31;
    const int mt = blockIdx.x, c = blockIdx.y;
    const int row0 = mt * 128;
    const int wm = wid & 1, wn = wid >> 1;
    const int mbase = wm * 64, nbase = wn * 32;

    auto load_stage = [&](int st, int kt) {
        char* base = smem + st * G1S;
        // A: fp32 U, 128 rows x 16 fp32-chunks, padded row stride 272B
#pragma unroll
        for (int q = 0; q < 16; ++q) {
            const int i = tid + 128 * q, r = i >> 4, j = i & 15;
            cpasync16(base + r * 272 + j * 16,
                      U + (size_t)(row0 + r) * PTOT + c * 256 + kt * 64 + j * 4);
        }
        // B: Sh, 64 rows x 8 chunks, swizzled
#pragma unroll
        for (int q = 0; q < 4; ++q) {
            const int i = tid + 128 * q, r = i >> 3, k8 = i & 7;
            cpasync16(base + BH_OFF + swz(r, k8),
                      g_Sh + (size_t)c * 64 * 256 + (size_t)r * 256 + kt * 64 + k8 * 8);
        }
    };

    float acc[4][4][4];
#pragma unroll
    for (int mi = 0; mi < 4; ++mi)
#pragma unroll
        for (int ni = 0; ni < 4; ++ni)
#pragma unroll
            for (int q = 0; q < 4; ++q) acc[mi][ni][q] = 0.f;

    load_stage(0, 0); cpcommit();
    load_stage(1, 1); cpcommit();

    const int atile = lane >> 3;
    const int ar_off = (lane & 7) + (atile & 1) * 8;
    const int ak_off = atile >> 1;
    const int btt = lane & 15;
    const int br_off = btt & 7;
    const int bk_off = btt >> 3;

#pragma unroll 1
    for (int kt = 0; kt < 4; ++kt) {
        const int st = kt & 1;
        cpwait<1>(); __syncthreads();
        char* base = smem + st * G1S;
        const uint32_t tb = sb + st * G1S;

        // convert own row (r = tid): fp32 staging -> fp16 swizzled A + STG g_Uh
        {
            char* ah = base + AH_OFF;
            __half* gdst = g_Uh + (size_t)(row0 + tid) * PTOT + c * 256 + kt * 64;
#pragma unroll
            for (int k8 = 0; k8 < 8; ++k8) {
                const float4 a = *(const float4*)(base + tid * 272 + (2 * k8) * 16);
                const float4 b = *(const float4*)(base + tid * 272 + (2 * k8 + 1) * 16);
                uint4 v;
                v.x = h2u(__floats2half2_rn(a.x, a.y));
                v.y = h2u(__floats2half2_rn(a.z, a.w));
                v.z = h2u(__floats2half2_rn(b.x, b.y));
                v.w = h2u(__floats2half2_rn(b.z, b.w));
                *(uint4*)(ah + swz(tid, k8)) = v;
                *(uint4*)(gdst + k8 * 8) = v;
            }
        }
        __syncthreads();   // Ah visible to all warps

#pragma unroll
        for (int ks = 0; ks < 4; ++ks) {
            uint32_t bh[4][2];
#pragma unroll
            for (int ni = 0; ni < 4; ++ni) {
                const int r = nbase + ni * 8 + br_off;
                ldmx2(bh[ni], tb + BH_OFF + swz(r, 2 * ks + bk_off));
            }
#pragma unroll
            for (int mi = 0; mi < 4; ++mi) {
                const int r = mbase + mi * 16 + ar_off;
                uint32_t ah[4];
                ldmx4(ah, tb + AH_OFF + swz(r, 2 * ks + ak_off));
#pragma unroll
                for (int ni = 0; ni < 4; ++ni)
                    mma16816(acc[mi][ni], ah, bh[ni]);
            }
        }
        __syncthreads();
        if (kt < 2) load_stage(st, kt + 2);
        cpcommit();
    }

    // epilogue -> g_xloc [row][c][64]
#pragma unroll
    for (int mi = 0; mi < 4; ++mi) {
        const int r0 = row0 + mbase + mi * 16 + (lane >> 2);
#pragma unroll
        for (int ni = 0; ni < 4; ++ni) {
            const int n = nbase + ni * 8 + (lane & 3) * 2;
            float* d0 = g_xloc + ((size_t)r0 * NCH + c) * 64 + n;
            float* d1 = g_xloc + ((size_t)(r0 + 8) * NCH + c) * 64 + n;
            *(float2*)d0 = make_float2(acc[mi][ni][0], acc[mi][ni][1]);
            *(float2*)d1 = make_float2(acc[mi][ni][2], acc[mi][ni][3]);
        }
    }
}

// =====================================================================
// 4. Phase B: all 32 P matrices resident in smem, xloc prefetched.
//    Emits xin as fp16.
// =====================================================================
#define PB_T 128
__global__ __launch_bounds__(PB_T)
void phaseB_kernel() {
    extern __shared__ float sP[];   // [32][1024] in processing order
    const int tid = threadIdx.x;
    const int d = blockIdx.y;
    const int row = blockIdx.x * PB_T + tid;

    for (int q = tid; q < 32 * 256; q += PB_T) {
        const int ci = q >> 8;
        const int c = d ? (NCH - 1 - ci) : ci;
        ((float4*)sP)[q] = ((const float4*)(g_P2 + (size_t)(d * NCH + c) * 1024))[q & 255];
    }
    __syncthreads();

    ull xp[16];
#pragma unroll
    for (int ip = 0; ip < 16; ++ip) xp[ip] = 0;

    float4 xl[8];
    auto ldxloc = [&](int ci) {
        const int c = d ? (NCH - 1 - ci) : ci;
        const float4* p = (const float4*)(g_xloc + ((size_t)row * NCH + c) * 64 + d * 32);
#pragma unroll
        for (int q = 0; q < 8; ++q) xl[q] = p[q];
    };
    ldxloc(0);

#pragma unroll 1
    for (int ci = 0; ci < NCH; ++ci) {
        const int c = d ? (NCH - 1 - ci) : ci;
        const size_t xoff = ((size_t)row * NCH + c) * 64 + d * 32;

        ull acc[16];
#pragma unroll
        for (int q = 0; q < 8; ++q) {
            acc[2 * q]     = pack2(xl[q].x, xl[q].y);
            acc[2 * q + 1] = pack2(xl[q].z, xl[q].w);
        }
        if (ci + 1 < NCH) ldxloc(ci + 1);

#pragma unroll
        for (int ip = 0; ip < 16; ++ip) {
            float x0, x1; unpack2(xp[ip], x0, x1);
            ((__half2*)(g_xinh + xoff))[ip] =
                __halves2half2(__float2half_rn(x0), __float2half_rn(x1));

            const ull xx0 = dup2(x0), xx1 = dup2(x1);
            const ulonglong2* pr0 = (const ulonglong2*)&sP[ci * 1024 + (2 * ip) * DS];
            const ulonglong2* pr1 = (const ulonglong2*)&sP[ci * 1024 + (2 * ip + 1) * DS];
#pragma unroll
            for (int t = 0; t < 8; ++t) {
                const ulonglong2 p0 = pr0[t];
                acc[2 * t]     = fma2(p0.x, xx0, acc[2 * t]);
                acc[2 * t + 1] = fma2(p0.y, xx0, acc[2 * t + 1]);
            }
#pragma unroll
            for (int t = 0; t < 8; ++t) {
                const ulonglong2 p1 = pr1[t];
                acc[2 * t]     = fma2(p1.x, xx1, acc[2 * t]);
                acc[2 * t + 1] = fma2(p1.y, xx1, acc[2 * t + 1]);
            }
        }
#pragma unroll
        for (int ip = 0; ip < 16; ++ip) xp[ip] = acc[ip];
    }
}

// =====================================================================
// 5. GEMM2 (fp16 single-term): out[128x256] = A[128x320] x Th^T + bias
//    FULL N per CTA. 256 thr = 8 warps (2m x 4n), warp tile 64x64.
//    stage 48KB = A 16K | Bh 32K; 2 stages (96KB)      [R14 config]
// =====================================================================
#define G2S 49152
__global__ __launch_bounds__(256)
void gemm2_kernel(const float* __restrict__ bias, float* __restrict__ out) {
    extern __shared__ char smem[];
    const uint32_t sb = (uint32_t)__cvta_generic_to_shared(smem);
    const int tid = threadIdx.x, wid = tid >> 5, lane = tid & 31;
    const int mt = blockIdx.x, c = blockIdx.y;
    const int row0 = mt * 128;
    const int wm = wid & 1, wn = wid >> 1;
    const int mbase = wm * 64, nbase = wn * 64;

    auto load_stage = [&](int st, int kt) {
        char* base = smem + st * G2S;
#pragma unroll
        for (int q = 0; q < 4; ++q) {
            const int i = tid + 256 * q, r = i >> 3, k8 = i & 7;
            const __half* src = (kt < 4)
                ? g_Uh + (size_t)(row0 + r) * PTOT + c * 256 + kt * 64 + k8 * 8
                : g_xinh + ((size_t)(row0 + r) * NCH + c) * 64 + k8 * 8;
            cpasync16(base + swz(r, k8), src);
        }
#pragma unroll
        for (int q = 0; q < 8; ++q) {
            const int i = tid + 256 * q, r = i >> 3, k8 = i & 7;
            const size_t g = (size_t)c * 256 * 320 + (size_t)r * 320 + kt * 64 + k8 * 8;
            cpasync16(base + 16384 + swz(r, k8), g_Th + g);
        }
    };

    float acc[4][8][4];
#pragma unroll
    for (int mi = 0; mi < 4; ++mi)
#pragma unroll
        for (int ni = 0; ni < 8; ++ni)
#pragma unroll
            for (int q = 0; q < 4; ++q) acc[mi][ni][q] = 0.f;

    load_stage(0, 0); cpcommit();
    load_stage(1, 1); cpcommit();

    const int atile = lane >> 3;
    const int ar_off = (lane & 7) + (atile & 1) * 8;
    const int ak_off = atile >> 1;
    const int btt = lane & 15;
    const int br_off = btt & 7;
    const int bk_off = btt >> 3;

#pragma unroll 1
    for (int kt = 0; kt < 5; ++kt) {
        const int st = kt & 1;
        cpwait<1>(); __syncthreads();
        const uint32_t tb = sb + st * G2S;
#pragma unroll
        for (int ks = 0; ks < 4; ++ks) {
            uint32_t bh[8][2];
#pragma unroll
            for (int ni = 0; ni < 8; ++ni) {
                const int r = nbase + ni * 8 + br_off;
                ldmx2(bh[ni], tb + 16384 + swz(r, 2 * ks + bk_off));
            }
#pragma unroll
            for (int mi = 0; mi < 4; ++mi) {
                const int r = mbase + mi * 16 + ar_off;
                uint32_t ah[4];
                ldmx4(ah, tb + swz(r, 2 * ks + ak_off));
#pragma unroll
                for (int ni = 0; ni < 8; ++ni)
                    mma16816(acc[mi][ni], ah, bh[ni]);
            }
        }
        __syncthreads();
        if (kt < 3) load_stage(st, kt + 2);
        cpcommit();
    }

    // epilogue: + bias, store float2 per tile-row
#pragma unroll
    for (int mi = 0; mi < 4; ++mi) {
        const int r0 = row0 + mbase + mi * 16 + (lane >> 2);
#pragma unroll
        for (int ni = 0; ni < 8; ++ni) {
            const int n = nbase + ni * 8 + (lane & 3) * 2;
            const float2 bv = *(const float2*)(bias + c * 256 + n);
            float* d0 = out + (size_t)r0 * PTOT + c * 256 + n;
            float* d1 = out + (size_t)(r0 + 8) * PTOT + c * 256 + n;
            *(float2*)d0 = make_float2(acc[mi][ni][0] + bv.x, acc[mi][ni][1] + bv.y);
            *(float2*)d1 = make_float2(acc[mi][ni][2] + bv.x, acc[mi][ni][3] + bv.y);
        }
    }
}

// =====================================================================
extern "C" void kernel_launch(void* const* d_in, const int* in_sizes, int n_in,
                              void* d_out, int out_size) {
    const float* U    = (const float*)d_in[0];
    const float* A    = (const float*)d_in[1];
    const float* B    = (const float*)d_in[2];
    const float* C    = (const float*)d_in[3];
    const float* D    = (const float*)d_in[4];
    const float* E    = (const float*)d_in[5];
    const float* F    = (const float*)d_in[6];
    const float* G    = (const float*)d_in[7];
    const float* bias = (const float*)d_in[8];
    float* out = (float*)d_out;

    cudaFuncSetAttribute(gemm1_kernel, cudaFuncAttributeMaxDynamicSharedMemorySize, 2 * G1S);
    cudaFuncSetAttribute(gemm2_kernel, cudaFuncAttributeMaxDynamicSharedMemorySize, 2 * G2S);
    cudaFuncSetAttribute(phaseB_kernel, cudaFuncAttributeMaxDynamicSharedMemorySize, 32 * 1024 * 4);

    strip_kernel<<<dim3(NCH, LCH, 2), 128>>>(A, B, C, D, E, F, G);
    mn_kernel<<<dim3(NCH, 2), 256>>>(A, C, E, G);
    gemm1_kernel<<<dim3(BATCH / 128, NCH), 128, 2 * G1S>>>(U);
    phaseB_kernel<<<dim3(BATCH / PB_T, 2), PB_T, 32 * 1024 * 4>>>();
    gemm2_kernel<<<dim3(BATCH / 128, NCH), 256, 2 * G2S>>>(bias, out);
}

// round 16
// speedup vs baseline: 1.2715x; 1.0799x over previous
#include <cuda_runtime.h>
#include <cuda_fp16.h>
#include <cstdint>

#define BATCH 4096
#define NST   512
#define IO    16
#define DS    32
#define PTOT  8192
#define NCH   32
#define LCH   16

typedef unsigned long long ull;

// ---------------- device scratch (static; no mallocs) ----------------
__device__ __align__(16) __half g_Uh[(size_t)BATCH * PTOT];            // fp16(U), written by gemm1
__device__ __align__(16) __half g_Th[(size_t)NCH * 256 * 320];         // T^T per chunk [n][k]
__device__ __align__(16) __half g_Sh[(size_t)NCH * 64 * 256];          // S^T per chunk [n][k]
__device__ __align__(16) float g_xloc[(size_t)BATCH * NCH * 64];       // [row][c][64]
__device__ __align__(16) __half g_xinh[(size_t)BATCH * NCH * 64];      // fp16(xin)
__device__ float g_P2[2 * NCH * DS * DS];

// ---------------- f32x2 helpers ----------------
__device__ __forceinline__ ull pack2(float lo, float hi) {
    ull r; asm("mov.b64 %0, {%1, %2};" : "=l"(r) : "f"(lo), "f"(hi)); return r;
}
__device__ __forceinline__ ull dup2(float v) { return pack2(v, v); }
__device__ __forceinline__ void unpack2(ull p, float& lo, float& hi) {
    asm("mov.b64 {%0, %1}, %2;" : "=f"(lo), "=f"(hi) : "l"(p));
}
__device__ __forceinline__ ull fma2(ull a, ull b, ull c) {
    ull r; asm("fma.rn.f32x2 %0, %1, %2, %3;" : "=l"(r) : "l"(a), "l"(b), "l"(c)); return r;
}

// ---------------- cp.async helpers ----------------
__device__ __forceinline__ void cpasync16(void* s, const void* g) {
    uint32_t sa = (uint32_t)__cvta_generic_to_shared(s);
    asm volatile("cp.async.cg.shared.global [%0], [%1], 16;" :: "r"(sa), "l"(g));
}
__device__ __forceinline__ void cpcommit() { asm volatile("cp.async.commit_group;"); }
template<int N> __device__ __forceinline__ void cpwait() {
    asm volatile("cp.async.wait_group %0;" :: "n"(N));
}

// ---------------- mma.sync / ldmatrix helpers (fp16) ----------------
__device__ __forceinline__ void ldmx4(uint32_t* r, uint32_t addr) {
    asm volatile("ldmatrix.sync.aligned.m8n8.x4.shared.b16 {%0,%1,%2,%3}, [%4];"
        : "=r"(r[0]), "=r"(r[1]), "=r"(r[2]), "=r"(r[3]) : "r"(addr));
}
__device__ __forceinline__ void ldmx2(uint32_t* r, uint32_t addr) {
    asm volatile("ldmatrix.sync.aligned.m8n8.x2.shared.b16 {%0,%1}, [%2];"
        : "=r"(r[0]), "=r"(r[1]) : "r"(addr));
}
__device__ __forceinline__ void mma16816(float* c, const uint32_t* a, const uint32_t* b) {
    asm volatile(
        "mma.sync.aligned.m16n8k16.row.col.f32.f16.f16.f32 "
        "{%0,%1,%2,%3}, {%4,%5,%6,%7}, {%8,%9}, {%0,%1,%2,%3};"
        : "+f"(c[0]), "+f"(c[1]), "+f"(c[2]), "+f"(c[3])
        : "r"(a[0]), "r"(a[1]), "r"(a[2]), "r"(a[3]), "r"(b[0]), "r"(b[1]));
}
// swizzled smem offset: logical (row r, 16B chunk k8) in a [*,64]fp16 tile
__device__ __forceinline__ uint32_t swz(int r, int k8) {
    return (uint32_t)(r * 128 + ((k8 ^ (r & 7)) << 4));
}
__device__ __forceinline__ uint32_t h2u(__half2 h) {
    uint32_t r; memcpy(&r, &h, 4); return r;
}

// =====================================================================
// 1. Strip precompute -> T^T (fp16) input blocks + S^T columns
// =====================================================================
__global__ __launch_bounds__(128)
void strip_kernel(const float* __restrict__ A, const float* __restrict__ B,
                  const float* __restrict__ C, const float* __restrict__ D,
                  const float* __restrict__ E, const float* __restrict__ F,
                  const float* __restrict__ G) {
    __shared__ float sV[2][DS][IO];
    __shared__ float sW2[DS][DS];
    __shared__ float sW1[IO][DS];
    const int tid = threadIdx.x;
    const int c = blockIdx.x, s = blockIdx.y, d = blockIdx.z;
    const int k0 = c * LCH;
    __half* Th = g_Th + (size_t)c * 256 * 320;

    const float* src0 = ((d == 0) ? B : F) + (size_t)(k0 + s) * 512;
    for (int e = tid; e < 512; e += 128) sV[0][e >> 4][e & 15] = src0[e];
    if (d == 0) {
        const float* Ds = D + (size_t)(k0 + s) * 256;
        for (int e = tid; e < 256; e += 128) {
            const int o = e >> 4, i = e & 15;
            Th[(size_t)(s * 16 + o) * 320 + s * 16 + i] = __float2half_rn(Ds[o * 16 + i]);
        }
    }
    __syncthreads();

    int pb = 0;
    const int nsteps = (d == 0) ? (LCH - 1 - s) : s;
    for (int step = 0; step < nsteps; ++step) {
        const int t = (d == 0) ? (s + 1 + step) : (s - 1 - step);
        const int k = k0 + t;
        const float* W2 = ((d == 0) ? A : E) + (size_t)k * 1024;
        const float* W1 = ((d == 0) ? C : G) + (size_t)k * 512;
        for (int e = tid; e < 1024; e += 128) sW2[e >> 5][e & 31] = W2[e];
        for (int e = tid; e < 512;  e += 128) sW1[e >> 5][e & 31] = W1[e];
        __syncthreads();
        for (int e = tid; e < 256; e += 128) {
            const int o = e >> 4, i = e & 15;
            float acc = 0.f;
#pragma unroll
            for (int l = 0; l < DS; ++l) acc += sW1[o][l] * sV[pb][l][i];
            Th[(size_t)(t * 16 + o) * 320 + s * 16 + i] = __float2half_rn(acc);
        }
        for (int e = tid; e < 512; e += 128) {
            const int j = e >> 4, i = e & 15;
            float acc = 0.f;
#pragma unroll
            for (int l = 0; l < DS; ++l) acc += sW2[j][l] * sV[pb][l][i];
            sV[pb ^ 1][j][i] = acc;
        }
        __syncthreads();
        pb ^= 1;
    }
    for (int e = tid; e < 512; e += 128) {
        const int j = e >> 4, i = e & 15;
        g_Sh[(size_t)c * 64 * 256 + (size_t)(d * 32 + j) * 256 + s * 16 + i] =
            __float2half_rn(sV[pb][j][i]);
    }
}

// =====================================================================
// 2. M/N correction rows of T^T + propagators
// =====================================================================
__global__ __launch_bounds__(256)
void mn_kernel(const float* __restrict__ A, const float* __restrict__ C,
               const float* __restrict__ E, const float* __restrict__ G) {
    __shared__ float sV[2][DS][DS];
    __shared__ float sW2[DS][DS];
    __shared__ float sW1[IO][DS];
    const int tid = threadIdx.x;
    const int c = blockIdx.x, d = blockIdx.y;
    const int k0 = c * LCH;
    __half* Th = g_Th + (size_t)c * 256 * 320;

    for (int e = tid; e < 1024; e += 256)
        sV[0][e >> 5][e & 31] = ((e >> 5) == (e & 31)) ? 1.f : 0.f;
    __syncthreads();

    int pb = 0;
    for (int step = 0; step < LCH; ++step) {
        const int t = (d == 0) ? step : (LCH - 1 - step);
        const int k = k0 + t;
        const float* W2 = ((d == 0) ? A : E) + (size_t)k * 1024;
        const float* W1 = ((d == 0) ? C : G) + (size_t)k * 512;
        for (int e = tid; e < 1024; e += 256) sW2[e >> 5][e & 31] = W2[e];
        for (int e = tid; e < 512;  e += 256) sW1[e >> 5][e & 31] = W1[e];
        __syncthreads();
        for (int e = tid; e < 512; e += 256) {
            const int o = e >> 5, j = e & 31;
            float acc = 0.f;
#pragma unroll
            for (int l = 0; l < DS; ++l) acc += sW1[o][l] * sV[pb][l][j];
            Th[(size_t)(t * 16 + o) * 320 + 256 + d * 32 + j] = __float2half_rn(acc);
        }
        for (int e = tid; e < 1024; e += 256) {
            const int i = e >> 5, j = e & 31;
            float acc = 0.f;
#pragma unroll
            for (int l = 0; l < DS; ++l) acc += sW2[i][l] * sV[pb][l][j];
            sV[pb ^ 1][i][j] = acc;
        }
        __syncthreads();
        pb ^= 1;
    }
    for (int e = tid; e < 1024; e += 256) {
        const int i = e >> 5, j = e & 31;
        g_P2[(size_t)(d * NCH + c) * 1024 + j * 32 + i] = sV[pb][i][j];
    }
}

// =====================================================================
// 3. GEMM1 (fp16 single-term, fused U-convert):
//    xloc[128x64] = fp16(U)[128x256] x Sh^T ; also writes g_Uh.
//    stage 58KB = Af32 34816(pad 272B/row) | Ah 16K | Bh 8K; 2 stages.
// =====================================================================
#define G1S 59392
#define AH_OFF 34816
#define BH_OFF 51200
__global__ __launch_bounds__(128)
void gemm1_kernel(const float* __restrict__ U) {
    extern __shared__ char smem[];
    const uint32_t sb = (uint32_t)__cvta_generic_to_shared(smem);
    const int tid = threadIdx.x, wid = tid >> 5, lane = tid & 31;
    const int mt = blockIdx.x, c = blockIdx.y;
    const int row0 = mt * 128;
    const int wm = wid & 1, wn = wid >> 1;
    const int mbase = wm * 64, nbase = wn * 32;

    auto load_stage = [&](int st, int kt) {
        char* base = smem + st * G1S;
#pragma unroll
        for (int q = 0; q < 16; ++q) {
            const int i = tid + 128 * q, r = i >> 4, j = i & 15;
            cpasync16(base + r * 272 + j * 16,
                      U + (size_t)(row0 + r) * PTOT + c * 256 + kt * 64 + j * 4);
        }
#pragma unroll
        for (int q = 0; q < 4; ++q) {
            const int i = tid + 128 * q, r = i >> 3, k8 = i & 7;
            cpasync16(base + BH_OFF + swz(r, k8),
                      g_Sh + (size_t)c * 64 * 256 + (size_t)r * 256 + kt * 64 + k8 * 8);
        }
    };

    float acc[4][4][4];
#pragma unroll
    for (int mi = 0; mi < 4; ++mi)
#pragma unroll
        for (int ni = 0; ni < 4; ++ni)
#pragma unroll
            for (int q = 0; q < 4; ++q) acc[mi][ni][q] = 0.f;

    load_stage(0, 0); cpcommit();
    load_stage(1, 1); cpcommit();

    const int atile = lane >> 3;
    const int ar_off = (lane & 7) + (atile & 1) * 8;
    const int ak_off = atile >> 1;
    const int btt = lane & 15;
    const int br_off = btt & 7;
    const int bk_off = btt >> 3;

#pragma unroll 1
    for (int kt = 0; kt < 4; ++kt) {
        const int st = kt & 1;
        cpwait<1>(); __syncthreads();
        char* base = smem + st * G1S;
        const uint32_t tb = sb + st * G1S;

        // convert own row (r = tid): fp32 staging -> fp16 swizzled A + STG g_Uh
        {
            char* ah = base + AH_OFF;
            __half* gdst = g_Uh + (size_t)(row0 + tid) * PTOT + c * 256 + kt * 64;
#pragma unroll
            for (int k8 = 0; k8 < 8; ++k8) {
                const float4 a = *(const float4*)(base + tid * 272 + (2 * k8) * 16);
                const float4 b = *(const float4*)(base + tid * 272 + (2 * k8 + 1) * 16);
                uint4 v;
                v.x = h2u(__floats2half2_rn(a.x, a.y));
                v.y = h2u(__floats2half2_rn(a.z, a.w));
                v.z = h2u(__floats2half2_rn(b.x, b.y));
                v.w = h2u(__floats2half2_rn(b.z, b.w));
                *(uint4*)(ah + swz(tid, k8)) = v;
                *(uint4*)(gdst + k8 * 8) = v;
            }
        }
        __syncthreads();

#pragma unroll
        for (int ks = 0; ks < 4; ++ks) {
            uint32_t bh[4][2];
#pragma unroll
            for (int ni = 0; ni < 4; ++ni) {
                const int r = nbase + ni * 8 + br_off;
                ldmx2(bh[ni], tb + BH_OFF + swz(r, 2 * ks + bk_off));
            }
#pragma unroll
            for (int mi = 0; mi < 4; ++mi) {
                const int r = mbase + mi * 16 + ar_off;
                uint32_t ah[4];
                ldmx4(ah, tb + AH_OFF + swz(r, 2 * ks + ak_off));
#pragma unroll
                for (int ni = 0; ni < 4; ++ni)
                    mma16816(acc[mi][ni], ah, bh[ni]);
            }
        }
        __syncthreads();
        if (kt < 2) load_stage(st, kt + 2);
        cpcommit();
    }

#pragma unroll
    for (int mi = 0; mi < 4; ++mi) {
        const int r0 = row0 + mbase + mi * 16 + (lane >> 2);
#pragma unroll
        for (int ni = 0; ni < 4; ++ni) {
            const int n = nbase + ni * 8 + (lane & 3) * 2;
            float* d0 = g_xloc + ((size_t)r0 * NCH + c) * 64 + n;
            float* d1 = g_xloc + ((size_t)(r0 + 8) * NCH + c) * 64 + n;
            *(float2*)d0 = make_float2(acc[mi][ni][0], acc[mi][ni][1]);
            *(float2*)d1 = make_float2(acc[mi][ni][2], acc[mi][ni][3]);
        }
    }
}

// =====================================================================
// 4. Phase B v3: 4 threads per row (sub owns 8 state entries).
//    x exchanged through padded smem; P fully smem-resident.
//    256 thr = 64 rows per CTA; grid (64, 2).
// =====================================================================
#define XST 36   // padded float stride per row
__global__ __launch_bounds__(256)
void phaseB_kernel() {
    extern __shared__ char smemraw[];
    float* sP = (float*)smemraw;                       // [32][1024] processing order
    float* sX = (float*)(smemraw + 32 * 1024 * 4);     // [64][XST]
    const int tid = threadIdx.x;
    const int d = blockIdx.y;
    const int sub = tid & 3, rl = tid >> 2;            // local row 0..63
    const int row = blockIdx.x * 64 + rl;
    float* xrow = sX + rl * XST;

    for (int q = tid; q < 32 * 256; q += 256) {
        const int ci = q >> 8;
        const int c = d ? (NCH - 1 - ci) : ci;
        ((float4*)sP)[q] = ((const float4*)(g_P2 + (size_t)(d * NCH + c) * 1024))[q & 255];
    }
    *(float4*)(xrow + sub * 8)     = make_float4(0.f, 0.f, 0.f, 0.f);
    *(float4*)(xrow + sub * 8 + 4) = make_float4(0.f, 0.f, 0.f, 0.f);
    __syncthreads();

    float4 xl[2];
    auto ldxloc = [&](int ci) {
        const int c = d ? (NCH - 1 - ci) : ci;
        const float4* p = (const float4*)(g_xloc + ((size_t)row * NCH + c) * 64 + d * 32 + sub * 8);
        xl[0] = p[0]; xl[1] = p[1];
    };
    ldxloc(0);

#pragma unroll 1
    for (int ci = 0; ci < NCH; ++ci) {
        const int c = d ? (NCH - 1 - ci) : ci;
        const size_t xoff = ((size_t)row * NCH + c) * 64 + d * 32 + sub * 8;

        // own 8 current-x entries -> xin fp16
        const float4 x0 = *(const float4*)(xrow + sub * 8);
        const float4 x1 = *(const float4*)(xrow + sub * 8 + 4);
        {
            uint4 v;
            v.x = h2u(__floats2half2_rn(x0.x, x0.y));
            v.y = h2u(__floats2half2_rn(x0.z, x0.w));
            v.z = h2u(__floats2half2_rn(x1.x, x1.y));
            v.w = h2u(__floats2half2_rn(x1.z, x1.w));
            *(uint4*)(g_xinh + xoff) = v;
        }

        ull acc[4];
        acc[0] = pack2(xl[0].x, xl[0].y);
        acc[1] = pack2(xl[0].z, xl[0].w);
        acc[2] = pack2(xl[1].x, xl[1].y);
        acc[3] = pack2(xl[1].z, xl[1].w);
        if (ci + 1 < NCH) ldxloc(ci + 1);

        const float* Pc = sP + ci * 1024 + sub * 8;
#pragma unroll
        for (int j = 0; j < DS; ++j) {
            const ull xx = dup2(xrow[j]);
            const ulonglong2 pv = *(const ulonglong2*)(Pc + j * 32);
            const ulonglong2 pw = *(const ulonglong2*)(Pc + j * 32 + 4);
            acc[0] = fma2(pv.x, xx, acc[0]);
            acc[1] = fma2(pv.y, xx, acc[1]);
            acc[2] = fma2(pw.x, xx, acc[2]);
            acc[3] = fma2(pw.y, xx, acc[3]);
        }
        __syncthreads();   // all reads of xrow done
        {
            float a0, a1, a2, a3, a4, a5, a6, a7;
            unpack2(acc[0], a0, a1); unpack2(acc[1], a2, a3);
            unpack2(acc[2], a4, a5); unpack2(acc[3], a6, a7);
            *(float4*)(xrow + sub * 8)     = make_float4(a0, a1, a2, a3);
            *(float4*)(xrow + sub * 8 + 4) = make_float4(a4, a5, a6, a7);
        }
        __syncthreads();   // new x visible
    }
}

// =====================================================================
// 5. GEMM2 (fp16 single-term): out[128x256] = A[128x320] x Th^T + bias
//    FULL N per CTA. 256 thr = 8 warps (2m x 4n), warp tile 64x64.
//    stage 48KB = A 16K | Bh 32K; 2 stages (96KB)
// =====================================================================
#define G2S 49152
__global__ __launch_bounds__(256)
void gemm2_kernel(const float* __restrict__ bias, float* __restrict__ out) {
    extern __shared__ char smem[];
    const uint32_t sb = (uint32_t)__cvta_generic_to_shared(smem);
    const int tid = threadIdx.x, wid = tid >> 5, lane = tid & 31;
    const int mt = blockIdx.x, c = blockIdx.y;
    const int row0 = mt * 128;
    const int wm = wid & 1, wn = wid >> 1;
    const int mbase = wm * 64, nbase = wn * 64;

    auto load_stage = [&](int st, int kt) {
        char* base = smem + st * G2S;
#pragma unroll
        for (int q = 0; q < 4; ++q) {
            const int i = tid + 256 * q, r = i >> 3, k8 = i & 7;
            const __half* src = (kt < 4)
                ? g_Uh + (size_t)(row0 + r) * PTOT + c * 256 + kt * 64 + k8 * 8
                : g_xinh + ((size_t)(row0 + r) * NCH + c) * 64 + k8 * 8;
            cpasync16(base + swz(r, k8), src);
        }
#pragma unroll
        for (int q = 0; q < 8; ++q) {
            const int i = tid + 256 * q, r = i >> 3, k8 = i & 7;
            const size_t g = (size_t)c * 256 * 320 + (size_t)r * 320 + kt * 64 + k8 * 8;
            cpasync16(base + 16384 + swz(r, k8), g_Th + g);
        }
    };

    float acc[4][8][4];
#pragma unroll
    for (int mi = 0; mi < 4; ++mi)
#pragma unroll
        for (int ni = 0; ni < 8; ++ni)
#pragma unroll
            for (int q = 0; q < 4; ++q) acc[mi][ni][q] = 0.f;

    load_stage(0, 0); cpcommit();
    load_stage(1, 1); cpcommit();

    const int atile = lane >> 3;
    const int ar_off = (lane & 7) + (atile & 1) * 8;
    const int ak_off = atile >> 1;
    const int btt = lane & 15;
    const int br_off = btt & 7;
    const int bk_off = btt >> 3;

#pragma unroll 1
    for (int kt = 0; kt < 5; ++kt) {
        const int st = kt & 1;
        cpwait<1>(); __syncthreads();
        const uint32_t tb = sb + st * G2S;
#pragma unroll
        for (int ks = 0; ks < 4; ++ks) {
            uint32_t bh[8][2];
#pragma unroll
            for (int ni = 0; ni < 8; ++ni) {
                const int r = nbase + ni * 8 + br_off;
                ldmx2(bh[ni], tb + 16384 + swz(r, 2 * ks + bk_off));
            }
#pragma unroll
            for (int mi = 0; mi < 4; ++mi) {
                const int r = mbase + mi * 16 + ar_off;
                uint32_t ah[4];
                ldmx4(ah, tb + swz(r, 2 * ks + ak_off));
#pragma unroll
                for (int ni = 0; ni < 8; ++ni)
                    mma16816(acc[mi][ni], ah, bh[ni]);
            }
        }
        __syncthreads();
        if (kt < 3) load_stage(st, kt + 2);
        cpcommit();
    }

#pragma unroll
    for (int mi = 0; mi < 4; ++mi) {
        const int r0 = row0 + mbase + mi * 16 + (lane >> 2);
#pragma unroll
        for (int ni = 0; ni < 8; ++ni) {
            const int n = nbase + ni * 8 + (lane & 3) * 2;
            const float2 bv = *(const float2*)(bias + c * 256 + n);
            float* d0 = out + (size_t)r0 * PTOT + c * 256 + n;
            float* d1 = out + (size_t)(r0 + 8) * PTOT + c * 256 + n;
            *(float2*)d0 = make_float2(acc[mi][ni][0] + bv.x, acc[mi][ni][1] + bv.y);
            *(float2*)d1 = make_float2(acc[mi][ni][2] + bv.x, acc[mi][ni][3] + bv.y);
        }
    }
}

// =====================================================================
extern "C" void kernel_launch(void* const* d_in, const int* in_sizes, int n_in,
                              void* d_out, int out_size) {
    const float* U    = (const float*)d_in[0];
    const float* A    = (const float*)d_in[1];
    const float* B    = (const float*)d_in[2];
    const float* C    = (const float*)d_in[3];
    const float* D    = (const float*)d_in[4];
    const float* E    = (const float*)d_in[5];
    const float* F    = (const float*)d_in[6];
    const float* G    = (const float*)d_in[7];
    const float* bias = (const float*)d_in[8];
    float* out = (float*)d_out;

    const int pbsmem = 32 * 1024 * 4 + 64 * XST * 4;
    cudaFuncSetAttribute(gemm1_kernel, cudaFuncAttributeMaxDynamicSharedMemorySize, 2 * G1S);
    cudaFuncSetAttribute(gemm2_kernel, cudaFuncAttributeMaxDynamicSharedMemorySize, 2 * G2S);
    cudaFuncSetAttribute(phaseB_kernel, cudaFuncAttributeMaxDynamicSharedMemorySize, pbsmem);

    strip_kernel<<<dim3(NCH, LCH, 2), 128>>>(A, B, C, D, E, F, G);
    mn_kernel<<<dim3(NCH, 2), 256>>>(A, C, E, G);
    gemm1_kernel<<<dim3(BATCH / 128, NCH), 128, 2 * G1S>>>(U);
    phaseB_kernel<<<dim3(BATCH / 64, 2), 256, pbsmem>>>();
    gemm2_kernel<<<dim3(BATCH / 128, NCH), 256, 2 * G2S>>>(bias, out);
}